// round 4
// baseline (speedup 1.0000x reference)
#include <cuda_runtime.h>
#include <math.h>

#define NN   20000
#define BB   2
#define TT   12
#define FIN  9
#define HH   64
#define EE   200000
#define ROWS (BB*NN)   // 40000

#define GRU_BLOCKS ((ROWS + 255) / 256)   // 157
#define L9_BLOCKS  ((ROWS + 63) / 64)     // 625
#define K1_BLOCKS  ((ROWS + 127) / 128)   // 313
#define XROWS      (BB * TT * NN)         // 480000

// ---------------- scratch (device globals; no allocations allowed) ----------
__device__ int   g_cnt[NN];        // zero at start of every launch (scan resets after use)
__device__ int   g_fill[NN];       // zero at start of every launch (enc resets after use)
__device__ int   g_ptr[NN + 1];
__device__ float g_deginv[NN];
__device__ int2  g_csr_sw[EE];     // (src, float_as_int(w))
__device__ __align__(16) float g_y1[ROWS * HH];
__device__ __align__(16) float g_t9p[ROWS * 16];      // padded to 16 floats/row
__device__ __align__(16) float g_xr9[ROWS * FIN];
__device__ __align__(16) float g_h[ROWS * FIN];
__device__ __align__(16) float g_x16[(long)XROWS * 16];  // padded graph copy
__device__ __align__(16) float g_outs[(long)XROWS * FIN];
__device__ float g_v[19];

// ---------------- helpers ----------------------------------------------------
__device__ __forceinline__ float elu_f(float v) { return v > 0.f ? v : expm1f(v); }

__device__ __forceinline__ void ffma2(unsigned long long& d,
                                      unsigned long long a, unsigned long long b) {
    asm("fma.rn.f32x2 %0, %1, %2, %0;" : "+l"(d) : "l"(a), "l"(b));
}
__device__ __forceinline__ float2 u2f2(unsigned long long u) {
    float2 r; asm("mov.b64 {%0, %1}, %2;" : "=f"(r.x), "=f"(r.y) : "l"(u)); return r;
}

// ---------------- setup -------------------------------------------------------
// prep: zero g_h, build padded x16 from graph, count in-degrees (g_cnt starts 0).
__global__ void __launch_bounds__(256) prep_kernel(const float* __restrict__ graph,
                                                   const int* __restrict__ edst) {
    int i = blockIdx.x * 256 + threadIdx.x;
    if (i < ROWS * FIN) g_h[i] = 0.f;
    if (i < XROWS) {
        float v[16];
        #pragma unroll
        for (int f = 0; f < 16; f++) v[f] = 0.f;
        const float* gp = graph + (long)i * 9;
        #pragma unroll
        for (int f = 0; f < 9; f++) v[f] = gp[f];
        float4* dst = (float4*)(g_x16 + (long)i * 16);
        dst[0] = make_float4(v[0], v[1], v[2], v[3]);
        dst[1] = make_float4(v[4], v[5], v[6], v[7]);
        dst[2] = make_float4(v[8], v[9], v[10], v[11]);
        dst[3] = make_float4(v[12], v[13], v[14], v[15]);
    }
    if (i < EE) atomicAdd(&g_cnt[edst[i]], 1);
}

// scan: prefix-sum degrees -> g_ptr, deginv; resets g_cnt; also folds in vprep.
__global__ void __launch_bounds__(1024) scan_kernel(
    const float* __restrict__ encW, const float* __restrict__ encb,
    const float* __restrict__ decW, const float* __restrict__ decb) {
    __shared__ int sh[1024];
    __shared__ int carry;
    int tid = threadIdx.x;
    if (tid == 0) { carry = 0; g_ptr[0] = 0; }
    __syncthreads();
    for (int base = 0; base < NN; base += 1024) {
        int i = base + tid;
        int v = (i < NN) ? g_cnt[i] : 0;
        if (i < NN) { g_deginv[i] = 1.0f / fmaxf((float)v, 1.0f); g_cnt[i] = 0; }
        sh[tid] = v;
        __syncthreads();
        #pragma unroll
        for (int off = 1; off < 1024; off <<= 1) {
            int t = (tid >= off) ? sh[tid - off] : 0;
            __syncthreads();
            sh[tid] += t;
            __syncthreads();
        }
        if (i < NN) g_ptr[i + 1] = carry + sh[tid];
        __syncthreads();
        if (tid == 0) carry += sh[1023];
        __syncthreads();
    }
    // vprep: collapse encoder+decoder (linear o linear)
    if (tid < 18) {
        float s = 0.f;
        for (int j = 0; j < 64; j++) s = fmaf(encW[tid * 64 + j], decW[j], s);
        g_v[tid] = s;
    } else if (tid == 18) {
        float s = decb[0];
        for (int j = 0; j < 64; j++) s = fmaf(encb[j], decW[j], s);
        g_v[18] = s;
    }
}

__global__ void fill_kernel(const int* __restrict__ src, const int* __restrict__ dst,
                            const float* __restrict__ w) {
    int e = blockIdx.x * 256 + threadIdx.x;
    if (e < EE) {
        int d = dst[e];
        int pos = g_ptr[d] + atomicAdd(&g_fill[d], 1);
        g_csr_sw[pos] = make_int2(src[e], __float_as_int(w[e]));
    }
}

// ============================================================================
// lin64: fused sage2 — warp-cooperative CSR-mean agg(d=64) of y1 +
//        [agg|x] @ [W2l;W2r] (K=128, packed f32x2 FMA) + bias + elu,
//        epilogue t9p = y2@W3l (padded), xr9 = y2@W3r (packed f32x2).
// 256 threads, 128 rows/block.
// ============================================================================
#define SAX_STRIDE 132
#define SM64_FLOATS (8192 + 1152 + 64 + 128 * SAX_STRIDE)
#define SM64_BYTES  (SM64_FLOATS * 4)

__global__ void __launch_bounds__(256) lin64_kernel(
    const float* __restrict__ W2l, const float* __restrict__ W2r,
    const float* __restrict__ b2,
    const float* __restrict__ W3l, const float* __restrict__ W3r)
{
    extern __shared__ __align__(16) float sm[];
    float* sW2 = sm;                 // [64 k-pairs][64 f][2] interleaved
    float* sW3 = sW2 + 8192;         // [2 m][32 k-pairs][9 f][2] interleaved
    float* sb  = sW3 + 1152;         // [64]
    float* sax = sb + 64;            // [128][132]: cols 0..63 agg, 64..127 x

    int tid = threadIdx.x;
    // interleave W2 pairs over k: sW2[(k2*64+f)*2+p] = W[2k2+p][f], W = [W2l;W2r]
    for (int i = tid; i < 8192; i += 256) {
        int f = i & 63, kk = i >> 6;
        float v = (kk < 64) ? W2l[kk * 64 + f] : W2r[(kk - 64) * 64 + f];
        sW2[((kk >> 1) * 64 + f) * 2 + (kk & 1)] = v;
    }
    // interleave W3 pairs over k
    for (int i = tid; i < 1152; i += 256) {
        int m = (i >= 576);
        int rem = i - m * 576;
        int kk = rem / 9, f = rem % 9;
        float v = m ? W3r[kk * 9 + f] : W3l[kk * 9 + f];
        sW3[m * 576 + ((kk >> 1) * 9 + f) * 2 + (kk & 1)] = v;
    }
    if (tid < 64) sb[tid] = b2[tid];

    int row0 = blockIdx.x * 128;
    int warp = tid >> 5, lane = tid & 31;
    int e2 = lane >> 4, q = lane & 15;

    // -------- warp-cooperative gather: warp w handles rows [w*16, w*16+16) ----
    const float4* y1v = (const float4*)g_y1;
    for (int rr = warp * 16; rr < warp * 16 + 16; rr++) {
        int row = row0 + rr;
        if (row >= ROWS) break;
        int b = row / NN, n = row % NN;
        long ybase = (long)b * NN * 16;      // float4 units
        int s = g_ptr[n], endj = g_ptr[n + 1];
        float4 acc = make_float4(0.f, 0.f, 0.f, 0.f);
        for (int j = s + e2; j < endj; j += 2) {
            int2 sw = g_csr_sw[j];
            float wt = __int_as_float(sw.y);
            float4 v = y1v[ybase + (long)sw.x * 16 + q];
            acc.x = fmaf(wt, v.x, acc.x);
            acc.y = fmaf(wt, v.y, acc.y);
            acc.z = fmaf(wt, v.z, acc.z);
            acc.w = fmaf(wt, v.w, acc.w);
        }
        acc.x += __shfl_xor_sync(0xffffffffu, acc.x, 16);
        acc.y += __shfl_xor_sync(0xffffffffu, acc.y, 16);
        acc.z += __shfl_xor_sync(0xffffffffu, acc.z, 16);
        acc.w += __shfl_xor_sync(0xffffffffu, acc.w, 16);
        if (lane < 16) {
            float dv = g_deginv[n];
            acc.x *= dv; acc.y *= dv; acc.z *= dv; acc.w *= dv;
            *(float4*)&sax[rr * SAX_STRIDE + q * 4] = acc;
        } else {
            *(float4*)&sax[rr * SAX_STRIDE + 64 + q * 4] = y1v[ybase + (long)n * 16 + q];
        }
    }
    __syncthreads();

    // -------- GEMM: 8 rows x 4 cols per thread, K=128 as 64 f32x2 pairs -------
    int tx = tid & 15, ty = tid >> 4;
    int f0 = tx * 4, r0 = ty * 8;
    unsigned long long acc2[8][4];
    #pragma unroll
    for (int i = 0; i < 8; i++)
        #pragma unroll
        for (int j = 0; j < 4; j++) acc2[i][j] = 0ull;

    const unsigned long long* w2 = (const unsigned long long*)sW2;
    #pragma unroll 2
    for (int k2 = 0; k2 < 64; k2++) {
        const unsigned long long* wp = w2 + (k2 * 64 + f0);
        ulonglong2 wa = *(const ulonglong2*)(wp);
        ulonglong2 wb = *(const ulonglong2*)(wp + 2);
        #pragma unroll
        for (int i = 0; i < 8; i++) {
            unsigned long long a2 =
                *(const unsigned long long*)(sax + (r0 + i) * SAX_STRIDE + 2 * k2);
            ffma2(acc2[i][0], a2, wa.x);
            ffma2(acc2[i][1], a2, wa.y);
            ffma2(acc2[i][2], a2, wb.x);
            ffma2(acc2[i][3], a2, wb.y);
        }
    }
    __syncthreads();   // all GEMM reads of sax complete

    // stash elu(y2) tile into sax cols 0..63
    #pragma unroll
    for (int i = 0; i < 8; i++) {
        float4 v;
        float2 p0 = u2f2(acc2[i][0]);
        float2 p1 = u2f2(acc2[i][1]);
        float2 p2 = u2f2(acc2[i][2]);
        float2 p3 = u2f2(acc2[i][3]);
        v.x = elu_f(p0.x + p0.y + sb[f0 + 0]);
        v.y = elu_f(p1.x + p1.y + sb[f0 + 1]);
        v.z = elu_f(p2.x + p2.y + sb[f0 + 2]);
        v.w = elu_f(p3.x + p3.y + sb[f0 + 3]);
        *(float4*)(sax + (r0 + i) * SAX_STRIDE + f0) = v;
    }
    __syncthreads();

    // -------- epilogue: t9p = y2@W3l, xr9 = y2@W3r (packed pairs over k) ------
    {
        int err2 = tid & 127;       // row within tile
        int m = tid >> 7;           // 0 -> t9p, 1 -> xr9
        int grow = row0 + err2;
        const float* yrow = sax + err2 * SAX_STRIDE;
        const unsigned long long* w3p = (const unsigned long long*)sW3 + m * 288;
        unsigned long long o2[9];
        #pragma unroll
        for (int f = 0; f < 9; f++) o2[f] = 0ull;
        #pragma unroll 4
        for (int k2 = 0; k2 < 32; k2++) {
            unsigned long long y2p = *(const unsigned long long*)(yrow + 2 * k2);
            const unsigned long long* wk = w3p + k2 * 9;
            #pragma unroll
            for (int f = 0; f < 9; f++) ffma2(o2[f], y2p, wk[f]);
        }
        if (grow < ROWS) {
            if (m == 0) {
                float* dst = g_t9p + (long)grow * 16;
                #pragma unroll
                for (int f = 0; f < 9; f++) { float2 p = u2f2(o2[f]); dst[f] = p.x + p.y; }
            } else {
                float* dst = g_xr9 + (long)grow * 9;
                #pragma unroll
                for (int f = 0; f < 9; f++) { float2 p = u2f2(o2[f]); dst[f] = p.x + p.y; }
            }
        }
    }
}

// ============================================================================
// Combo kernel: blocks [0, gru_blocks) run gru(t); the rest run lin9(t+1).
// Both use warp-cooperative gathers (8 edges x 3 float4-lanes per row).
// ============================================================================
__global__ void __launch_bounds__(256) combo_kernel(
    int t, int gru_blocks,
    const float* __restrict__ W1l, const float* __restrict__ W1r,
    const float* __restrict__ b1,
    const float* __restrict__ b3,
    const float* __restrict__ Wih, const float* __restrict__ Whh,
    const float* __restrict__ bih, const float* __restrict__ bhh)
{
    int tid = threadIdx.x;
    int warp = tid >> 5, lane = tid & 31;
    int q = lane >> 3, e = lane & 7;      // q: float4 slot (0..2 active), e: edge slot

    if ((int)blockIdx.x < gru_blocks) {
        // ---------------- GRU(t): sage3 agg(d=9, padded) + elu + GRU ----------
        __shared__ float swih[9 * 27], swhh[9 * 27], sb3[9], sbi[27], sbh[27];
        __shared__ __align__(16) float s_agg[256 * 12];
        const float* wih = Wih + t * 243;
        const float* whh = Whh + t * 243;
        for (int i = tid; i < 243; i += 256) { swih[i] = wih[i]; swhh[i] = whh[i]; }
        if (tid < 27) { sbi[tid] = bih[t * 27 + tid]; sbh[tid] = bhh[t * 27 + tid]; }
        if (tid < 9) sb3[tid] = b3[t * 9 + tid];

        int row0 = blockIdx.x * 256;
        const float4* t9v = (const float4*)g_t9p;
        for (int rr = warp * 32; rr < warp * 32 + 32; rr++) {
            int row = row0 + rr;
            if (row >= ROWS) break;
            int b = row / NN, n = row % NN;
            long tbase = (long)b * NN * 4;       // float4 units
            int s = g_ptr[n], endj = g_ptr[n + 1];
            float4 acc = make_float4(0.f, 0.f, 0.f, 0.f);
            if (q < 3) {
                for (int j = s + e; j < endj; j += 8) {
                    int2 sw = g_csr_sw[j];
                    float wt = __int_as_float(sw.y);
                    float4 v = t9v[tbase + (long)sw.x * 4 + q];
                    acc.x = fmaf(wt, v.x, acc.x);
                    acc.y = fmaf(wt, v.y, acc.y);
                    acc.z = fmaf(wt, v.z, acc.z);
                    acc.w = fmaf(wt, v.w, acc.w);
                }
            }
            #pragma unroll
            for (int d = 4; d; d >>= 1) {
                acc.x += __shfl_down_sync(0xffffffffu, acc.x, d, 8);
                acc.y += __shfl_down_sync(0xffffffffu, acc.y, d, 8);
                acc.z += __shfl_down_sync(0xffffffffu, acc.z, d, 8);
                acc.w += __shfl_down_sync(0xffffffffu, acc.w, d, 8);
            }
            if (e == 0 && q < 3) {
                float dv = g_deginv[n];
                acc.x *= dv; acc.y *= dv; acc.z *= dv; acc.w *= dv;
                *(float4*)&s_agg[rr * 12 + q * 4] = acc;
            }
        }
        __syncthreads();

        int idx = row0 + tid;
        if (idx >= ROWS) return;
        int b = idx / NN, n = idx % NN;

        const float* ag = s_agg + tid * 12;
        const float* xr = g_xr9 + (long)idx * 9;
        float y[9];
        #pragma unroll
        for (int f = 0; f < 9; f++) y[f] = elu_f(ag[f] + xr[f] + sb3[f]);

        float h[9];
        const float* hp = g_h + (long)idx * 9;
        #pragma unroll
        for (int f = 0; f < 9; f++) h[f] = hp[f];

        float gi[27], gh[27];
        #pragma unroll
        for (int j = 0; j < 27; j++) { gi[j] = sbi[j]; gh[j] = sbh[j]; }
        #pragma unroll
        for (int k = 0; k < 9; k++) {
            float yk = y[k], hk = h[k];
            #pragma unroll
            for (int j = 0; j < 27; j++) {
                gi[j] = fmaf(yk, swih[k * 27 + j], gi[j]);
                gh[j] = fmaf(hk, swhh[k * 27 + j], gh[j]);
            }
        }

        float* hw = g_h + (long)idx * 9;
        float* op = g_outs + (((long)b * TT + t) * NN + n) * 9;
        #pragma unroll
        for (int f = 0; f < 9; f++) {
            float r  = 1.f / (1.f + expf(-(gi[f] + gh[f])));
            float z  = 1.f / (1.f + expf(-(gi[9 + f] + gh[9 + f])));
            float nv = tanhf(gi[18 + f] + r * gh[18 + f]);
            float hv = (1.f - z) * nv + z * h[f];
            hw[f] = hv;
            op[f] = hv;
        }
    } else {
        // ---------------- lin9(t+1): agg(d=9) + [agg|x]@[W1l;W1r] + elu -------
        __shared__ __align__(16) float sW9[18 * 64];
        __shared__ __align__(16) float sb9[64];
        __shared__ __align__(16) float sax9[64 * 24];  // agg 0..11 | x 12..23

        int tn = t + 1;
        const float* w1l = W1l + tn * 576;
        const float* w1r = W1r + tn * 576;
        for (int i = tid; i < 1152; i += 256)
            sW9[i] = (i < 576) ? w1l[i] : w1r[i - 576];
        if (tid < 64) sb9[tid] = b1[tn * 64 + tid];

        int lb = blockIdx.x - gru_blocks;
        int row0 = lb * 64;
        const float4* xv = (const float4*)g_x16;

        for (int rr = warp * 8; rr < warp * 8 + 8; rr++) {
            int row = row0 + rr;
            if (row >= ROWS) break;
            int b = row / NN, n = row % NN;
            long xbase = ((long)b * TT + tn) * NN * 4;   // float4 units
            int s = g_ptr[n], endj = g_ptr[n + 1];
            float4 acc = make_float4(0.f, 0.f, 0.f, 0.f);
            if (q < 3) {
                for (int j = s + e; j < endj; j += 8) {
                    int2 sw = g_csr_sw[j];
                    float wt = __int_as_float(sw.y);
                    float4 v = xv[xbase + (long)sw.x * 4 + q];
                    acc.x = fmaf(wt, v.x, acc.x);
                    acc.y = fmaf(wt, v.y, acc.y);
                    acc.z = fmaf(wt, v.z, acc.z);
                    acc.w = fmaf(wt, v.w, acc.w);
                }
            }
            #pragma unroll
            for (int d = 4; d; d >>= 1) {
                acc.x += __shfl_down_sync(0xffffffffu, acc.x, d, 8);
                acc.y += __shfl_down_sync(0xffffffffu, acc.y, d, 8);
                acc.z += __shfl_down_sync(0xffffffffu, acc.z, d, 8);
                acc.w += __shfl_down_sync(0xffffffffu, acc.w, d, 8);
            }
            if (e == 0 && q < 3) {
                float dv = g_deginv[n];
                acc.x *= dv; acc.y *= dv; acc.z *= dv; acc.w *= dv;
                *(float4*)&sax9[rr * 24 + q * 4] = acc;
            }
            if (lane < 3)
                *(float4*)&sax9[rr * 24 + 12 + lane * 4] = xv[xbase + (long)n * 4 + lane];
        }
        __syncthreads();

        // GEMM: 4 rows x 4 cols per thread, K=18
        int tx = tid & 15, ty = tid >> 4;
        int f0 = tx * 4, r0 = ty * 4;
        float4 acc[4];
        {
            float4 bv = *(const float4*)&sb9[f0];
            #pragma unroll
            for (int i = 0; i < 4; i++) acc[i] = bv;
        }
        #pragma unroll
        for (int k = 0; k < 18; k++) {
            float4 w = *(const float4*)&sW9[k * 64 + f0];
            int ko = (k < 9) ? k : (3 + k);
            #pragma unroll
            for (int i = 0; i < 4; i++) {
                float a = sax9[(r0 + i) * 24 + ko];
                acc[i].x = fmaf(a, w.x, acc[i].x);
                acc[i].y = fmaf(a, w.y, acc[i].y);
                acc[i].z = fmaf(a, w.z, acc[i].z);
                acc[i].w = fmaf(a, w.w, acc[i].w);
            }
        }
        #pragma unroll
        for (int i = 0; i < 4; i++) {
            int row = row0 + r0 + i;
            if (row < ROWS) {
                float4 v = acc[i];
                v.x = elu_f(v.x); v.y = elu_f(v.y); v.z = elu_f(v.z); v.w = elu_f(v.w);
                *(float4*)(g_y1 + (long)row * 64 + f0) = v;
            }
        }
    }
}

// final collapsed encoder/decoder + mask; also resets g_fill for next replay
__global__ void __launch_bounds__(256) enc_kernel(const float* __restrict__ graph,
                                                  const float* __restrict__ tev,
                                                  float* __restrict__ out) {
    long i = (long)blockIdx.x * 256 + threadIdx.x;
    if (i < NN) g_fill[i] = 0;
    if (i >= (long)XROWS) return;
    int b = (int)(i / ((long)TT * NN));
    const float* o = g_outs + i * 9;
    float acc = g_v[18];
    #pragma unroll
    for (int f = 0; f < 9; f++) acc = fmaf(tev[b * 9 + f], g_v[9 + f], acc);
    #pragma unroll
    for (int f = 0; f < 9; f++) acc = fmaf(o[f], g_v[f], acc);
    out[i] = (graph[i * 9] != 0.f) ? acc : 0.f;
}

// ---------------- host ------------------------------------------------------
extern "C" void kernel_launch(void* const* d_in, const int* in_sizes, int n_in,
                              void* d_out, int out_size) {
    const float* graph = (const float*)d_in[0];
    const float* tev   = (const float*)d_in[1];
    const float* ew    = (const float*)d_in[3];
    const int*   esrc  = (const int*)d_in[4];
    const int*   edst  = (const int*)d_in[5];
    const float* W1l = (const float*)d_in[6];
    const float* b1  = (const float*)d_in[7];
    const float* W1r = (const float*)d_in[8];
    const float* W2l = (const float*)d_in[9];
    const float* b2  = (const float*)d_in[10];
    const float* W2r = (const float*)d_in[11];
    const float* W3l = (const float*)d_in[12];
    const float* b3  = (const float*)d_in[13];
    const float* W3r = (const float*)d_in[14];
    const float* Wih = (const float*)d_in[15];
    const float* Whh = (const float*)d_in[16];
    const float* bih = (const float*)d_in[17];
    const float* bhh = (const float*)d_in[18];
    const float* encW = (const float*)d_in[19];
    const float* encb = (const float*)d_in[20];
    const float* decW = (const float*)d_in[21];
    const float* decb = (const float*)d_in[22];
    float* out = (float*)d_out;

    cudaFuncSetAttribute(lin64_kernel,
                         cudaFuncAttributeMaxDynamicSharedMemorySize, SM64_BYTES);

    prep_kernel<<<(XROWS + 255) / 256, 256>>>(graph, edst);
    scan_kernel<<<1, 1024>>>(encW, encb, decW, decb);
    fill_kernel<<<(EE + 255) / 256, 256>>>(esrc, edst, ew);

    for (int t = 0; t < TT; t++) {
        int gb = (t == 0) ? 0 : GRU_BLOCKS;
        combo_kernel<<<gb + L9_BLOCKS, 256>>>(
            t - 1, gb, W1l, W1r, b1, b3, Wih, Whh, bih, bhh);
        lin64_kernel<<<K1_BLOCKS, 256, SM64_BYTES>>>(
            W2l + t * 4096, W2r + t * 4096, b2 + t * 64,
            W3l + t * 576, W3r + t * 576);
    }
    combo_kernel<<<GRU_BLOCKS, 256>>>(
        11, GRU_BLOCKS, W1l, W1r, b1, b3, Wih, Whh, bih, bhh);

    enc_kernel<<<(XROWS + 255) / 256, 256>>>(graph, tev, out);
}

// round 5
// speedup vs baseline: 1.1507x; 1.1507x over previous
#include <cuda_runtime.h>
#include <math.h>

#define NN   20000
#define BB   2
#define TT   12
#define FIN  9
#define HH   64
#define EE   200000
#define ROWS (BB*NN)   // 40000

#define GRU_BLOCKS ((ROWS + 255) / 256)   // 157
#define L9_BLOCKS  ((ROWS + 63) / 64)     // 625
#define K1_BLOCKS  ((ROWS + 127) / 128)   // 313
#define XROWS      (BB * TT * NN)         // 480000

// ---------------- scratch (device globals; no allocations allowed) ----------
__device__ int   g_cnt[NN];        // 0 at launch entry (scan resets after consuming)
__device__ int   g_fill[NN];       // 0 at fill entry (scan resets each launch)
__device__ int   g_ptr[NN + 1];
__device__ float g_deginv[NN];
__device__ int2  g_csr_sw[EE];     // (src, float_as_int(w))
__device__ __align__(16) float g_y1[ROWS * HH];
__device__ __align__(16) float g_t9p[ROWS * 16];        // 16-float padded rows; pad stays 0
__device__ __align__(16) float g_xr9[ROWS * FIN];
__device__ __align__(16) float g_h[ROWS * FIN];
__device__ __align__(16) float g_x16[(long)XROWS * 16]; // padded graph copy
__device__ float g_v[9];           // collapsed enc*dec weights for h-part
__device__ float g_vc[BB];         // per-batch constant (te-part + biases)

// ---------------- helpers ----------------------------------------------------
__device__ __forceinline__ float elu_f(float v) { return v > 0.f ? v : expm1f(v); }

__device__ __forceinline__ void ffma2(unsigned long long& d,
                                      unsigned long long a, unsigned long long b) {
    asm("fma.rn.f32x2 %0, %1, %2, %0;" : "+l"(d) : "l"(a), "l"(b));
}
__device__ __forceinline__ float2 u2f2(unsigned long long u) {
    float2 r; asm("mov.b64 {%0, %1}, %2;" : "=f"(r.x), "=f"(r.y) : "l"(u)); return r;
}

// ---------------- setup -------------------------------------------------------
// prep: zero g_h, build padded x16 from graph, count in-degrees.
__global__ void __launch_bounds__(256) prep_kernel(const float* __restrict__ graph,
                                                   const int* __restrict__ edst) {
    int i = blockIdx.x * 256 + threadIdx.x;
    if (i < ROWS * FIN) g_h[i] = 0.f;
    if (i < XROWS) {
        float v[16];
        #pragma unroll
        for (int f = 0; f < 16; f++) v[f] = 0.f;
        const float* gp = graph + (long)i * 9;
        #pragma unroll
        for (int f = 0; f < 9; f++) v[f] = gp[f];
        float4* dst = (float4*)(g_x16 + (long)i * 16);
        dst[0] = make_float4(v[0], v[1], v[2], v[3]);
        dst[1] = make_float4(v[4], v[5], v[6], v[7]);
        dst[2] = make_float4(v[8], v[9], v[10], v[11]);
        dst[3] = make_float4(v[12], v[13], v[14], v[15]);
    }
    if (i < EE) atomicAdd(&g_cnt[edst[i]], 1);
}

// scan: prefix-sum degrees -> g_ptr + deginv; resets g_cnt/g_fill; folds vprep.
__global__ void __launch_bounds__(1024) scan_kernel(
    const float* __restrict__ encW, const float* __restrict__ encb,
    const float* __restrict__ decW, const float* __restrict__ decb,
    const float* __restrict__ tev) {
    __shared__ int wsum[32];
    __shared__ int carry;
    __shared__ float sv[19];
    int tid = threadIdx.x;
    int lane = tid & 31, wid = tid >> 5;

    // collapsed encoder/decoder
    if (tid < 18) {
        float s = 0.f;
        for (int j = 0; j < 64; j++) s = fmaf(encW[tid * 64 + j], decW[j], s);
        sv[tid] = s;
    } else if (tid == 18) {
        float s = decb[0];
        for (int j = 0; j < 64; j++) s = fmaf(encb[j], decW[j], s);
        sv[18] = s;
    }
    if (tid == 0) { carry = 0; g_ptr[0] = 0; }
    __syncthreads();
    if (tid < 9) g_v[tid] = sv[tid];
    if (tid < BB) {
        float c = sv[18];
        #pragma unroll
        for (int f = 0; f < 9; f++) c = fmaf(tev[tid * 9 + f], sv[9 + f], c);
        g_vc[tid] = c;
    }

    for (int base = 0; base < NN; base += 1024) {
        int i = base + tid;
        int v = (i < NN) ? g_cnt[i] : 0;
        if (i < NN) {
            g_deginv[i] = 1.0f / fmaxf((float)v, 1.0f);
            g_cnt[i] = 0;
            g_fill[i] = 0;
        }
        int s = v;
        #pragma unroll
        for (int off = 1; off < 32; off <<= 1) {
            int tv = __shfl_up_sync(0xffffffffu, s, off);
            if (lane >= off) s += tv;
        }
        if (lane == 31) wsum[wid] = s;
        __syncthreads();
        if (wid == 0) {
            int ws = wsum[lane];
            #pragma unroll
            for (int off = 1; off < 32; off <<= 1) {
                int tv = __shfl_up_sync(0xffffffffu, ws, off);
                if (lane >= off) ws += tv;
            }
            wsum[lane] = ws;
        }
        __syncthreads();
        int excl = wid ? wsum[wid - 1] : 0;
        if (i < NN) g_ptr[i + 1] = carry + excl + s;
        __syncthreads();
        if (tid == 0) carry += wsum[31];
        __syncthreads();
    }
}

__global__ void fill_kernel(const int* __restrict__ src, const int* __restrict__ dst,
                            const float* __restrict__ w) {
    int e = blockIdx.x * 256 + threadIdx.x;
    if (e < EE) {
        int d = dst[e];
        int pos = g_ptr[d] + atomicAdd(&g_fill[d], 1);
        g_csr_sw[pos] = make_int2(src[e], __float_as_int(w[e]));
    }
}

// ============================================================================
// lin64: fused sage2 — lane-owns-feature CSR-mean agg(d=64) of y1 +
//        [agg|x] @ [W2l;W2r] (K=128, f32x2 FMA) + bias + elu,
//        epilogue t9p = y2@W3l (padded), xr9 = y2@W3r.
// 256 threads, 128 rows/block. One warp per row during gather (float2/lane).
// ============================================================================
#define SAX_STRIDE 132
#define SM64_FLOATS (8192 + 1152 + 64 + 128 * SAX_STRIDE)
#define SM64_BYTES  (SM64_FLOATS * 4)

__global__ void __launch_bounds__(256) lin64_kernel(
    const float* __restrict__ W2l, const float* __restrict__ W2r,
    const float* __restrict__ b2,
    const float* __restrict__ W3l, const float* __restrict__ W3r)
{
    extern __shared__ __align__(16) float sm[];
    float* sW2 = sm;                 // [64 k-pairs][64 f][2] interleaved
    float* sW3 = sW2 + 8192;         // [2 m][32 k-pairs][9 f][2] interleaved
    float* sb  = sW3 + 1152;         // [64]
    float* sax = sb + 64;            // [128][132]: cols 0..63 agg, 64..127 x

    int tid = threadIdx.x;
    for (int i = tid; i < 8192; i += 256) {
        int f = i & 63, kk = i >> 6;
        float v = (kk < 64) ? W2l[kk * 64 + f] : W2r[(kk - 64) * 64 + f];
        sW2[((kk >> 1) * 64 + f) * 2 + (kk & 1)] = v;
    }
    for (int i = tid; i < 1152; i += 256) {
        int m = (i >= 576);
        int rem = i - m * 576;
        int kk = rem / 9, f = rem % 9;
        float v = m ? W3r[kk * 9 + f] : W3l[kk * 9 + f];
        sW3[m * 576 + ((kk >> 1) * 9 + f) * 2 + (kk & 1)] = v;
    }
    if (tid < 64) sb[tid] = b2[tid];

    int row0 = blockIdx.x * 128;
    int warp = tid >> 5, lane = tid & 31;

    // -------- gather: one warp per row, lane owns 2 features ------------------
    #pragma unroll 1
    for (int i = 0; i < 16; i++) {
        int rr = warp * 16 + i;
        int row = row0 + rr;
        if (row < ROWS) {
            int b = row / NN, n = row % NN;
            const float* yb = g_y1 + (long)b * NN * 64;
            int s = g_ptr[n], e = g_ptr[n + 1];
            float2 acc = make_float2(0.f, 0.f);
            for (int j = s; j < e; j++) {
                int2 sw = g_csr_sw[j];                 // warp-uniform -> broadcast
                float wt = __int_as_float(sw.y);
                float2 v = *(const float2*)(yb + (long)sw.x * 64 + lane * 2);
                acc.x = fmaf(wt, v.x, acc.x);
                acc.y = fmaf(wt, v.y, acc.y);
            }
            float dv = g_deginv[n];
            float2 xv = *(const float2*)(yb + (long)n * 64 + lane * 2);
            *(float2*)(sax + rr * SAX_STRIDE + lane * 2) =
                make_float2(acc.x * dv, acc.y * dv);
            *(float2*)(sax + rr * SAX_STRIDE + 64 + lane * 2) = xv;
        }
    }
    __syncthreads();

    // -------- GEMM: 8 rows x 4 cols per thread, K=128 as 64 f32x2 pairs -------
    int tx = tid & 15, ty = tid >> 4;
    int f0 = tx * 4, r0 = ty * 8;
    unsigned long long acc2[8][4];
    #pragma unroll
    for (int i = 0; i < 8; i++)
        #pragma unroll
        for (int j = 0; j < 4; j++) acc2[i][j] = 0ull;

    const unsigned long long* w2 = (const unsigned long long*)sW2;
    #pragma unroll 2
    for (int k2 = 0; k2 < 64; k2++) {
        const unsigned long long* wp = w2 + (k2 * 64 + f0);
        ulonglong2 wa = *(const ulonglong2*)(wp);
        ulonglong2 wb = *(const ulonglong2*)(wp + 2);
        #pragma unroll
        for (int i = 0; i < 8; i++) {
            unsigned long long a2 =
                *(const unsigned long long*)(sax + (r0 + i) * SAX_STRIDE + 2 * k2);
            ffma2(acc2[i][0], a2, wa.x);
            ffma2(acc2[i][1], a2, wa.y);
            ffma2(acc2[i][2], a2, wb.x);
            ffma2(acc2[i][3], a2, wb.y);
        }
    }
    __syncthreads();

    // stash elu(y2) tile into sax cols 0..63
    #pragma unroll
    for (int i = 0; i < 8; i++) {
        float4 v;
        float2 p0 = u2f2(acc2[i][0]);
        float2 p1 = u2f2(acc2[i][1]);
        float2 p2 = u2f2(acc2[i][2]);
        float2 p3 = u2f2(acc2[i][3]);
        v.x = elu_f(p0.x + p0.y + sb[f0 + 0]);
        v.y = elu_f(p1.x + p1.y + sb[f0 + 1]);
        v.z = elu_f(p2.x + p2.y + sb[f0 + 2]);
        v.w = elu_f(p3.x + p3.y + sb[f0 + 3]);
        *(float4*)(sax + (r0 + i) * SAX_STRIDE + f0) = v;
    }
    __syncthreads();

    // epilogue: t9p = y2@W3l (padded rows), xr9 = y2@W3r
    {
        int err2 = tid & 127;
        int m = tid >> 7;
        int grow = row0 + err2;
        const float* yrow = sax + err2 * SAX_STRIDE;
        const unsigned long long* w3p = (const unsigned long long*)sW3 + m * 288;
        unsigned long long o2[9];
        #pragma unroll
        for (int f = 0; f < 9; f++) o2[f] = 0ull;
        #pragma unroll 4
        for (int k2 = 0; k2 < 32; k2++) {
            unsigned long long y2p = *(const unsigned long long*)(yrow + 2 * k2);
            const unsigned long long* wk = w3p + k2 * 9;
            #pragma unroll
            for (int f = 0; f < 9; f++) ffma2(o2[f], y2p, wk[f]);
        }
        if (grow < ROWS) {
            float* dst = m ? (g_xr9 + (long)grow * 9) : (g_t9p + (long)grow * 16);
            #pragma unroll
            for (int f = 0; f < 9; f++) { float2 p = u2f2(o2[f]); dst[f] = p.x + p.y; }
        }
    }
}

// ============================================================================
// Combo kernel: blocks [0, gru_blocks) run gru(t) (+ final output dot);
// the rest run lin9(t+1). Gathers: half-warp per row, lane owns feature.
// ============================================================================
__global__ void __launch_bounds__(256, 3) combo_kernel(
    int t, int gru_blocks,
    const float* __restrict__ W1l, const float* __restrict__ W1r,
    const float* __restrict__ b1,
    const float* __restrict__ b3,
    const float* __restrict__ Wih, const float* __restrict__ Whh,
    const float* __restrict__ bih, const float* __restrict__ bhh,
    float* __restrict__ out)
{
    int tid = threadIdx.x;
    int warp = tid >> 5, lane = tid & 31;
    int hh = lane >> 4, f16 = lane & 15;   // half-warp id, owned feature

    if ((int)blockIdx.x < gru_blocks) {
        // ---------------- GRU(t): sage3 agg(d=9) + elu + GRU + output ---------
        __shared__ float swih[9 * 27], swhh[9 * 27], sb3[9], sbi[27], sbh[27];
        __shared__ float sv9[9], svc[BB];
        __shared__ float s_agg[256 * 17];
        const float* wih = Wih + t * 243;
        const float* whh = Whh + t * 243;
        for (int i = tid; i < 243; i += 256) { swih[i] = wih[i]; swhh[i] = whh[i]; }
        if (tid < 27) { sbi[tid] = bih[t * 27 + tid]; sbh[tid] = bhh[t * 27 + tid]; }
        if (tid < 9) { sb3[tid] = b3[t * 9 + tid]; sv9[tid] = g_v[tid]; }
        if (tid < BB) svc[tid] = g_vc[tid];

        int row0 = blockIdx.x * 256;
        // gather: half-warp per row, lane owns 1 of 16 padded features
        #pragma unroll 1
        for (int p = 0; p < 16; p++) {
            int rr = warp * 32 + p * 2 + hh;
            int row = row0 + rr;
            if (row < ROWS) {
                int b = row / NN, n = row % NN;
                const float* tb = g_t9p + (long)b * NN * 16;
                int s = g_ptr[n], e = g_ptr[n + 1];
                float acc = 0.f;
                for (int j = s; j < e; j++) {
                    int2 sw = g_csr_sw[j];             // half-warp uniform
                    acc = fmaf(__int_as_float(sw.y), tb[(long)sw.x * 16 + f16], acc);
                }
                s_agg[rr * 17 + f16] = acc * g_deginv[n];
            }
        }
        __syncthreads();

        int idx = row0 + tid;
        if (idx >= ROWS) return;
        int b = idx / NN, n = idx % NN;

        const float* ag = s_agg + tid * 17;
        const float* xr = g_xr9 + (long)idx * 9;
        float y[9];
        #pragma unroll
        for (int f = 0; f < 9; f++) y[f] = elu_f(ag[f] + xr[f] + sb3[f]);

        float h[9];
        const float* hp = g_h + (long)idx * 9;
        #pragma unroll
        for (int f = 0; f < 9; f++) h[f] = hp[f];

        // merged accumulators: gs = gi+gh for r,z gates; gin/ghn separate
        float gs[18], gin[9], ghn[9];
        #pragma unroll
        for (int j = 0; j < 18; j++) gs[j] = sbi[j] + sbh[j];
        #pragma unroll
        for (int j = 0; j < 9; j++) { gin[j] = sbi[18 + j]; ghn[j] = sbh[18 + j]; }
        #pragma unroll
        for (int k = 0; k < 9; k++) {
            float yk = y[k], hk = h[k];
            const float* wi = swih + k * 27;
            const float* wh = swhh + k * 27;
            #pragma unroll
            for (int j = 0; j < 18; j++) gs[j] = fmaf(yk, wi[j], fmaf(hk, wh[j], gs[j]));
            #pragma unroll
            for (int j = 0; j < 9; j++) {
                gin[j] = fmaf(yk, wi[18 + j], gin[j]);
                ghn[j] = fmaf(hk, wh[18 + j], ghn[j]);
            }
        }

        long iout = ((long)b * TT + t) * NN + n;
        float dot = svc[b];
        float* hw = g_h + (long)idx * 9;
        #pragma unroll
        for (int f = 0; f < 9; f++) {
            float r  = 1.f / (1.f + expf(-gs[f]));
            float z  = 1.f / (1.f + expf(-gs[9 + f]));
            float nv = tanhf(gin[f] + r * ghn[f]);
            float hv = (1.f - z) * nv + z * h[f];
            hw[f] = hv;
            dot = fmaf(hv, sv9[f], dot);
        }
        float mask = g_x16[iout * 16];
        out[iout] = (mask != 0.f) ? dot : 0.f;
    } else {
        // ---------------- lin9(t+1): agg(d=9) + [agg|x]@[W1l;W1r] + elu -------
        __shared__ __align__(16) float sW9[18 * 64];
        __shared__ float sb9[64];
        __shared__ float sax9[64 * 33];   // agg 0..15 | x 16..31 (stride 33)

        int tn = t + 1;
        const float* w1l = W1l + tn * 576;
        const float* w1r = W1r + tn * 576;
        for (int i = tid; i < 1152; i += 256)
            sW9[i] = (i < 576) ? w1l[i] : w1r[i - 576];
        if (tid < 64) sb9[tid] = b1[tn * 64 + tid];

        int lb = blockIdx.x - gru_blocks;
        int row0 = lb * 64;
        const float* xb0 = g_x16;

        #pragma unroll 1
        for (int p = 0; p < 4; p++) {
            int rr = warp * 8 + p * 2 + hh;
            int row = row0 + rr;
            if (row < ROWS) {
                int b = row / NN, n = row % NN;
                const float* xb = xb0 + ((long)b * TT + tn) * NN * 16;
                int s = g_ptr[n], e = g_ptr[n + 1];
                float acc = 0.f;
                for (int j = s; j < e; j++) {
                    int2 sw = g_csr_sw[j];
                    acc = fmaf(__int_as_float(sw.y), xb[(long)sw.x * 16 + f16], acc);
                }
                sax9[rr * 33 + f16] = acc * g_deginv[n];
                sax9[rr * 33 + 16 + f16] = xb[(long)n * 16 + f16];
            }
        }
        __syncthreads();

        // GEMM: 4 rows x 4 cols per thread, K=18
        int tx = tid & 15, ty = tid >> 4;
        int f0 = tx * 4, r0 = ty * 4;
        float4 acc[4];
        {
            float4 bv = make_float4(sb9[f0], sb9[f0 + 1], sb9[f0 + 2], sb9[f0 + 3]);
            #pragma unroll
            for (int i = 0; i < 4; i++) acc[i] = bv;
        }
        #pragma unroll
        for (int k = 0; k < 18; k++) {
            float4 w = *(const float4*)&sW9[k * 64 + f0];
            int ko = (k < 9) ? k : (k + 7);
            #pragma unroll
            for (int i = 0; i < 4; i++) {
                float a = sax9[(r0 + i) * 33 + ko];
                acc[i].x = fmaf(a, w.x, acc[i].x);
                acc[i].y = fmaf(a, w.y, acc[i].y);
                acc[i].z = fmaf(a, w.z, acc[i].z);
                acc[i].w = fmaf(a, w.w, acc[i].w);
            }
        }
        #pragma unroll
        for (int i = 0; i < 4; i++) {
            int row = row0 + r0 + i;
            if (row < ROWS) {
                float4 v = acc[i];
                v.x = elu_f(v.x); v.y = elu_f(v.y); v.z = elu_f(v.z); v.w = elu_f(v.w);
                *(float4*)(g_y1 + (long)row * 64 + f0) = v;
            }
        }
    }
}

// ---------------- host ------------------------------------------------------
extern "C" void kernel_launch(void* const* d_in, const int* in_sizes, int n_in,
                              void* d_out, int out_size) {
    const float* graph = (const float*)d_in[0];
    const float* tev   = (const float*)d_in[1];
    const float* ew    = (const float*)d_in[3];
    const int*   esrc  = (const int*)d_in[4];
    const int*   edst  = (const int*)d_in[5];
    const float* W1l = (const float*)d_in[6];
    const float* b1  = (const float*)d_in[7];
    const float* W1r = (const float*)d_in[8];
    const float* W2l = (const float*)d_in[9];
    const float* b2  = (const float*)d_in[10];
    const float* W2r = (const float*)d_in[11];
    const float* W3l = (const float*)d_in[12];
    const float* b3  = (const float*)d_in[13];
    const float* W3r = (const float*)d_in[14];
    const float* Wih = (const float*)d_in[15];
    const float* Whh = (const float*)d_in[16];
    const float* bih = (const float*)d_in[17];
    const float* bhh = (const float*)d_in[18];
    const float* encW = (const float*)d_in[19];
    const float* encb = (const float*)d_in[20];
    const float* decW = (const float*)d_in[21];
    const float* decb = (const float*)d_in[22];
    float* out = (float*)d_out;

    cudaFuncSetAttribute(lin64_kernel,
                         cudaFuncAttributeMaxDynamicSharedMemorySize, SM64_BYTES);

    prep_kernel<<<(XROWS + 255) / 256, 256>>>(graph, edst);
    scan_kernel<<<1, 1024>>>(encW, encb, decW, decb, tev);
    fill_kernel<<<(EE + 255) / 256, 256>>>(esrc, edst, ew);

    for (int t = 0; t < TT; t++) {
        int gb = (t == 0) ? 0 : GRU_BLOCKS;
        combo_kernel<<<gb + L9_BLOCKS, 256>>>(
            t - 1, gb, W1l, W1r, b1, b3, Wih, Whh, bih, bhh, out);
        lin64_kernel<<<K1_BLOCKS, 256, SM64_BYTES>>>(
            W2l + t * 4096, W2r + t * 4096, b2 + t * 64,
            W3l + t * 576, W3r + t * 576);
    }
    combo_kernel<<<GRU_BLOCKS, 256>>>(
        11, GRU_BLOCKS, W1l, W1r, b1, b3, Wih, Whh, bih, bhh, out);
}

// round 6
// speedup vs baseline: 1.1995x; 1.0424x over previous
#include <cuda_runtime.h>
#include <math.h>

#define NN   20000
#define BB   2
#define TT   12
#define FIN  9
#define HH   64
#define EE   200000
#define ROWS (BB*NN)   // 40000

#define GRU_BLOCKS ((ROWS + 255) / 256)   // 157
#define L9_BLOCKS  ((ROWS + 63) / 64)     // 625
#define K1_BLOCKS  ((ROWS + 127) / 128)   // 313
#define XROWS      (BB * TT * NN)         // 480000

// ---------------- scratch (device globals; no allocations allowed) ----------
__device__ int   g_cnt[NN];
__device__ int   g_fill[NN];
__device__ int   g_ptr[NN + 1];
__device__ float g_deginv[NN];
__device__ int2  g_csr_sw[EE];     // (src, float_as_int(w))
__device__ __align__(16) float g_y1[ROWS * HH];
__device__ __align__(16) float g_t9p[ROWS * 16];        // padded rows; pad stays 0
__device__ __align__(16) float g_xr9[ROWS * FIN];
__device__ __align__(16) float g_h[ROWS * FIN];
__device__ __align__(16) float g_x16[(long)XROWS * 16]; // padded graph copy
__device__ float g_v[9];           // collapsed enc*dec weights (h part)
__device__ float g_vc[BB];         // per-batch constant (te part + biases)

// ---------------- helpers ----------------------------------------------------
__device__ __forceinline__ float elu_f(float v) { return v > 0.f ? v : expm1f(v); }

__device__ __forceinline__ void ffma2(unsigned long long& d,
                                      unsigned long long a, unsigned long long b) {
    asm("fma.rn.f32x2 %0, %1, %2, %0;" : "+l"(d) : "l"(a), "l"(b));
}
__device__ __forceinline__ float2 u2f2(unsigned long long u) {
    float2 r; asm("mov.b64 {%0, %1}, %2;" : "=f"(r.x), "=f"(r.y) : "l"(u)); return r;
}

// ---------------- setup -------------------------------------------------------
__global__ void __launch_bounds__(256) prep_kernel(const float* __restrict__ graph,
                                                   const int* __restrict__ edst) {
    int i = blockIdx.x * 256 + threadIdx.x;
    if (i < ROWS * FIN) g_h[i] = 0.f;
    if (i < XROWS) {
        float v[16];
        #pragma unroll
        for (int f = 0; f < 16; f++) v[f] = 0.f;
        const float* gp = graph + (long)i * 9;
        #pragma unroll
        for (int f = 0; f < 9; f++) v[f] = gp[f];
        float4* dst = (float4*)(g_x16 + (long)i * 16);
        dst[0] = make_float4(v[0], v[1], v[2], v[3]);
        dst[1] = make_float4(v[4], v[5], v[6], v[7]);
        dst[2] = make_float4(v[8], v[9], v[10], v[11]);
        dst[3] = make_float4(v[12], v[13], v[14], v[15]);
    }
    if (i < EE) atomicAdd(&g_cnt[edst[i]], 1);
}

__global__ void __launch_bounds__(1024) scan_kernel(
    const float* __restrict__ encW, const float* __restrict__ encb,
    const float* __restrict__ decW, const float* __restrict__ decb,
    const float* __restrict__ tev) {
    __shared__ int wsum[32];
    __shared__ int carry;
    __shared__ float sv[19];
    int tid = threadIdx.x;
    int lane = tid & 31, wid = tid >> 5;

    if (tid < 18) {
        float s = 0.f;
        for (int j = 0; j < 64; j++) s = fmaf(encW[tid * 64 + j], decW[j], s);
        sv[tid] = s;
    } else if (tid == 18) {
        float s = decb[0];
        for (int j = 0; j < 64; j++) s = fmaf(encb[j], decW[j], s);
        sv[18] = s;
    }
    if (tid == 0) { carry = 0; g_ptr[0] = 0; }
    __syncthreads();
    if (tid < 9) g_v[tid] = sv[tid];
    if (tid < BB) {
        float c = sv[18];
        #pragma unroll
        for (int f = 0; f < 9; f++) c = fmaf(tev[tid * 9 + f], sv[9 + f], c);
        g_vc[tid] = c;
    }

    for (int base = 0; base < NN; base += 1024) {
        int i = base + tid;
        int v = (i < NN) ? g_cnt[i] : 0;
        if (i < NN) {
            g_deginv[i] = 1.0f / fmaxf((float)v, 1.0f);
            g_cnt[i] = 0;
            g_fill[i] = 0;
        }
        int s = v;
        #pragma unroll
        for (int off = 1; off < 32; off <<= 1) {
            int tv = __shfl_up_sync(0xffffffffu, s, off);
            if (lane >= off) s += tv;
        }
        if (lane == 31) wsum[wid] = s;
        __syncthreads();
        if (wid == 0) {
            int ws = wsum[lane];
            #pragma unroll
            for (int off = 1; off < 32; off <<= 1) {
                int tv = __shfl_up_sync(0xffffffffu, ws, off);
                if (lane >= off) ws += tv;
            }
            wsum[lane] = ws;
        }
        __syncthreads();
        int excl = wid ? wsum[wid - 1] : 0;
        if (i < NN) g_ptr[i + 1] = carry + excl + s;
        __syncthreads();
        if (tid == 0) carry += wsum[31];
        __syncthreads();
    }
}

__global__ void fill_kernel(const int* __restrict__ src, const int* __restrict__ dst,
                            const float* __restrict__ w) {
    int e = blockIdx.x * 256 + threadIdx.x;
    if (e < EE) {
        int d = dst[e];
        int pos = g_ptr[d] + atomicAdd(&g_fill[d], 1);
        g_csr_sw[pos] = make_int2(src[e], __float_as_int(w[e]));
    }
}

// ============================================================================
// lin64: fused sage2 — agg(d=64) gather with 4 rows in flight per warp +
//        [agg|x] @ [W2l;W2r] (K=128, f32x2 FMA) + bias + elu,
//        epilogue t9p = y2@W3l (padded), xr9 = y2@W3r.
// ============================================================================
#define SAX_STRIDE 132
#define SM64_FLOATS (8192 + 1152 + 64 + 128 * SAX_STRIDE)
#define SM64_BYTES  (SM64_FLOATS * 4)

__global__ void __launch_bounds__(256) lin64_kernel(
    const float* __restrict__ W2l, const float* __restrict__ W2r,
    const float* __restrict__ b2,
    const float* __restrict__ W3l, const float* __restrict__ W3r)
{
    extern __shared__ __align__(16) float sm[];
    float* sW2 = sm;                 // [64 k-pairs][64 f][2]
    float* sW3 = sW2 + 8192;         // [2 m][32 k-pairs][9 f][2]
    float* sb  = sW3 + 1152;         // [64]
    float* sax = sb + 64;            // [128][132]: 0..63 agg | 64..127 x

    int tid = threadIdx.x;
    for (int i = tid; i < 8192; i += 256) {
        int f = i & 63, kk = i >> 6;
        float v = (kk < 64) ? W2l[kk * 64 + f] : W2r[(kk - 64) * 64 + f];
        sW2[((kk >> 1) * 64 + f) * 2 + (kk & 1)] = v;
    }
    for (int i = tid; i < 1152; i += 256) {
        int m = (i >= 576);
        int rem = i - m * 576;
        int kk = rem / 9, f = rem % 9;
        float v = m ? W3r[kk * 9 + f] : W3l[kk * 9 + f];
        sW3[m * 576 + ((kk >> 1) * 9 + f) * 2 + (kk & 1)] = v;
    }
    if (tid < 64) sb[tid] = b2[tid];

    int row0 = blockIdx.x * 128;
    int warp = tid >> 5, lane = tid & 31;

    // -------- gather: 4 rows in flight per warp, lane owns 2 features ---------
    #pragma unroll 1
    for (int pass = 0; pass < 4; pass++) {
        int rbase = warp * 16 + pass * 4;
        float2 acc[4];
        const float* yb[4];
        int sA[4], eA[4], nn_[4];
        int maxlen = 0;
        #pragma unroll
        for (int i = 0; i < 4; i++) {
            int row = row0 + rbase + i;
            acc[i] = make_float2(0.f, 0.f);
            if (row < ROWS) {
                int b = row / NN, n = row % NN;
                nn_[i] = n;
                yb[i] = g_y1 + (long)b * NN * 64;
                sA[i] = g_ptr[n]; eA[i] = g_ptr[n + 1];
                int len = eA[i] - sA[i];
                maxlen = len > maxlen ? len : maxlen;
            } else { nn_[i] = -1; yb[i] = g_y1; sA[i] = 0; eA[i] = 0; }
        }
        for (int k = 0; k < maxlen; k++) {
            #pragma unroll
            for (int i = 0; i < 4; i++) {
                int j = sA[i] + k;
                if (j < eA[i]) {
                    int2 sw = g_csr_sw[j];
                    float2 v = *(const float2*)(yb[i] + (long)sw.x * 64 + lane * 2);
                    float wt = __int_as_float(sw.y);
                    acc[i].x = fmaf(wt, v.x, acc[i].x);
                    acc[i].y = fmaf(wt, v.y, acc[i].y);
                }
            }
        }
        #pragma unroll
        for (int i = 0; i < 4; i++) {
            if (nn_[i] >= 0) {
                int rr = rbase + i;
                float dv = g_deginv[nn_[i]];
                *(float2*)(sax + rr * SAX_STRIDE + lane * 2) =
                    make_float2(acc[i].x * dv, acc[i].y * dv);
                *(float2*)(sax + rr * SAX_STRIDE + 64 + lane * 2) =
                    *(const float2*)(yb[i] + (long)nn_[i] * 64 + lane * 2);
            }
        }
    }
    __syncthreads();

    // -------- GEMM: 8 rows x 4 cols per thread, K=128 as 64 f32x2 pairs -------
    int tx = tid & 15, ty = tid >> 4;
    int f0 = tx * 4, r0 = ty * 8;
    unsigned long long acc2[8][4];
    #pragma unroll
    for (int i = 0; i < 8; i++)
        #pragma unroll
        for (int j = 0; j < 4; j++) acc2[i][j] = 0ull;

    const unsigned long long* w2 = (const unsigned long long*)sW2;
    #pragma unroll 2
    for (int k2 = 0; k2 < 64; k2++) {
        const unsigned long long* wp = w2 + (k2 * 64 + f0);
        ulonglong2 wa = *(const ulonglong2*)(wp);
        ulonglong2 wb = *(const ulonglong2*)(wp + 2);
        #pragma unroll
        for (int i = 0; i < 8; i++) {
            unsigned long long a2 =
                *(const unsigned long long*)(sax + (r0 + i) * SAX_STRIDE + 2 * k2);
            ffma2(acc2[i][0], a2, wa.x);
            ffma2(acc2[i][1], a2, wa.y);
            ffma2(acc2[i][2], a2, wb.x);
            ffma2(acc2[i][3], a2, wb.y);
        }
    }
    __syncthreads();

    #pragma unroll
    for (int i = 0; i < 8; i++) {
        float4 v;
        float2 p0 = u2f2(acc2[i][0]);
        float2 p1 = u2f2(acc2[i][1]);
        float2 p2 = u2f2(acc2[i][2]);
        float2 p3 = u2f2(acc2[i][3]);
        v.x = elu_f(p0.x + p0.y + sb[f0 + 0]);
        v.y = elu_f(p1.x + p1.y + sb[f0 + 1]);
        v.z = elu_f(p2.x + p2.y + sb[f0 + 2]);
        v.w = elu_f(p3.x + p3.y + sb[f0 + 3]);
        *(float4*)(sax + (r0 + i) * SAX_STRIDE + f0) = v;
    }
    __syncthreads();

    // epilogue: t9p = y2@W3l (padded rows), xr9 = y2@W3r
    {
        int err2 = tid & 127;
        int m = tid >> 7;
        int grow = row0 + err2;
        const float* yrow = sax + err2 * SAX_STRIDE;
        const unsigned long long* w3p = (const unsigned long long*)sW3 + m * 288;
        unsigned long long o2[9];
        #pragma unroll
        for (int f = 0; f < 9; f++) o2[f] = 0ull;
        #pragma unroll 4
        for (int k2 = 0; k2 < 32; k2++) {
            unsigned long long y2p = *(const unsigned long long*)(yrow + 2 * k2);
            const unsigned long long* wk = w3p + k2 * 9;
            #pragma unroll
            for (int f = 0; f < 9; f++) ffma2(o2[f], y2p, wk[f]);
        }
        if (grow < ROWS) {
            float* dst = m ? (g_xr9 + (long)grow * 9) : (g_t9p + (long)grow * 16);
            #pragma unroll
            for (int f = 0; f < 9; f++) { float2 p = u2f2(o2[f]); dst[f] = p.x + p.y; }
        }
    }
}

// ============================================================================
// Combo kernel: blocks [0, gru_blocks) run gru(t) (+ output dot);
// the rest run lin9(t+1). Gathers: half-warp per row slot, 4 rows in flight.
// ============================================================================
__global__ void __launch_bounds__(256) combo_kernel(
    int t, int gru_blocks,
    const float* __restrict__ W1l, const float* __restrict__ W1r,
    const float* __restrict__ b1,
    const float* __restrict__ b3,
    const float* __restrict__ Wih, const float* __restrict__ Whh,
    const float* __restrict__ bih, const float* __restrict__ bhh,
    float* __restrict__ out)
{
    int tid = threadIdx.x;
    int warp = tid >> 5, lane = tid & 31;
    int hh = lane >> 4, f16 = lane & 15;

    if ((int)blockIdx.x < gru_blocks) {
        // ---------------- GRU(t): sage3 agg(d=9) + elu + GRU + output ---------
        __shared__ float swih[9 * 27], swhh[9 * 27], sb3[9], sbi[27], sbh[27];
        __shared__ float sv9[9], svc[BB];
        __shared__ float s_agg[256 * 17];
        const float* wih = Wih + t * 243;
        const float* whh = Whh + t * 243;
        for (int i = tid; i < 243; i += 256) { swih[i] = wih[i]; swhh[i] = whh[i]; }
        if (tid < 27) { sbi[tid] = bih[t * 27 + tid]; sbh[tid] = bhh[t * 27 + tid]; }
        if (tid < 9) { sb3[tid] = b3[t * 9 + tid]; sv9[tid] = g_v[tid]; }
        if (tid < BB) svc[tid] = g_vc[tid];

        int row0 = blockIdx.x * 256;
        // gather: half-warp covers 16 rows, 4 rows in flight
        #pragma unroll 1
        for (int pass = 0; pass < 4; pass++) {
            int rbase = warp * 32 + hh * 16 + pass * 4;
            float acc[4];
            const float* tb[4];
            int sA[4], eA[4], nn_[4];
            int maxlen = 0;
            #pragma unroll
            for (int i = 0; i < 4; i++) {
                int row = row0 + rbase + i;
                acc[i] = 0.f;
                if (row < ROWS) {
                    int b = row / NN, n = row % NN;
                    nn_[i] = n;
                    tb[i] = g_t9p + (long)b * NN * 16;
                    sA[i] = g_ptr[n]; eA[i] = g_ptr[n + 1];
                    int len = eA[i] - sA[i];
                    maxlen = len > maxlen ? len : maxlen;
                } else { nn_[i] = -1; tb[i] = g_t9p; sA[i] = 0; eA[i] = 0; }
            }
            for (int k = 0; k < maxlen; k++) {
                #pragma unroll
                for (int i = 0; i < 4; i++) {
                    int j = sA[i] + k;
                    if (j < eA[i]) {
                        int2 sw = g_csr_sw[j];
                        acc[i] = fmaf(__int_as_float(sw.y),
                                      tb[i][(long)sw.x * 16 + f16], acc[i]);
                    }
                }
            }
            #pragma unroll
            for (int i = 0; i < 4; i++)
                if (nn_[i] >= 0)
                    s_agg[(rbase + i) * 17 + f16] = acc[i] * g_deginv[nn_[i]];
        }
        __syncthreads();

        int idx = row0 + tid;
        if (idx >= ROWS) return;
        int b = idx / NN, n = idx % NN;

        const float* ag = s_agg + tid * 17;
        const float* xr = g_xr9 + (long)idx * 9;
        float y[9];
        #pragma unroll
        for (int f = 0; f < 9; f++) y[f] = elu_f(ag[f] + xr[f] + sb3[f]);

        float h[9];
        const float* hp = g_h + (long)idx * 9;
        #pragma unroll
        for (int f = 0; f < 9; f++) h[f] = hp[f];

        float gs[18], gin[9], ghn[9];
        #pragma unroll
        for (int j = 0; j < 18; j++) gs[j] = sbi[j] + sbh[j];
        #pragma unroll
        for (int j = 0; j < 9; j++) { gin[j] = sbi[18 + j]; ghn[j] = sbh[18 + j]; }
        #pragma unroll
        for (int k = 0; k < 9; k++) {
            float yk = y[k], hk = h[k];
            const float* wi = swih + k * 27;
            const float* wh = swhh + k * 27;
            #pragma unroll
            for (int j = 0; j < 18; j++) gs[j] = fmaf(yk, wi[j], fmaf(hk, wh[j], gs[j]));
            #pragma unroll
            for (int j = 0; j < 9; j++) {
                gin[j] = fmaf(yk, wi[18 + j], gin[j]);
                ghn[j] = fmaf(hk, wh[18 + j], ghn[j]);
            }
        }

        long iout = ((long)b * TT + t) * NN + n;
        float dot = svc[b];
        float* hw = g_h + (long)idx * 9;
        #pragma unroll
        for (int f = 0; f < 9; f++) {
            float r  = 1.f / (1.f + expf(-gs[f]));
            float z  = 1.f / (1.f + expf(-gs[9 + f]));
            float nv = tanhf(gin[f] + r * ghn[f]);
            float hv = (1.f - z) * nv + z * h[f];
            hw[f] = hv;
            dot = fmaf(hv, sv9[f], dot);
        }
        float mask = g_x16[iout * 16];
        out[iout] = (mask != 0.f) ? dot : 0.f;
    } else {
        // ---------------- lin9(t+1): agg(d=9) + [agg|x]@[W1l;W1r] + elu -------
        __shared__ __align__(16) float sW9[18 * 64];
        __shared__ float sb9[64];
        __shared__ float sax9[64 * 33];   // agg 0..15 | x 16..31 (stride 33)

        int tn = t + 1;
        const float* w1l = W1l + tn * 576;
        const float* w1r = W1r + tn * 576;
        for (int i = tid; i < 1152; i += 256)
            sW9[i] = (i < 576) ? w1l[i] : w1r[i - 576];
        if (tid < 64) sb9[tid] = b1[tn * 64 + tid];

        int lb = blockIdx.x - gru_blocks;
        int row0 = lb * 64;

        // gather: half-warp covers 4 rows, all 4 in flight (one pass)
        {
            int rbase = warp * 8 + hh * 4;
            float acc[4];
            const float* xb[4];
            int sA[4], eA[4], nn_[4];
            int maxlen = 0;
            #pragma unroll
            for (int i = 0; i < 4; i++) {
                int row = row0 + rbase + i;
                acc[i] = 0.f;
                if (row < ROWS) {
                    int b = row / NN, n = row % NN;
                    nn_[i] = n;
                    xb[i] = g_x16 + ((long)b * TT + tn) * NN * 16;
                    sA[i] = g_ptr[n]; eA[i] = g_ptr[n + 1];
                    int len = eA[i] - sA[i];
                    maxlen = len > maxlen ? len : maxlen;
                } else { nn_[i] = -1; xb[i] = g_x16; sA[i] = 0; eA[i] = 0; }
            }
            for (int k = 0; k < maxlen; k++) {
                #pragma unroll
                for (int i = 0; i < 4; i++) {
                    int j = sA[i] + k;
                    if (j < eA[i]) {
                        int2 sw = g_csr_sw[j];
                        acc[i] = fmaf(__int_as_float(sw.y),
                                      xb[i][(long)sw.x * 16 + f16], acc[i]);
                    }
                }
            }
            #pragma unroll
            for (int i = 0; i < 4; i++) {
                if (nn_[i] >= 0) {
                    int rr = rbase + i;
                    sax9[rr * 33 + f16] = acc[i] * g_deginv[nn_[i]];
                    sax9[rr * 33 + 16 + f16] = xb[i][(long)nn_[i] * 16 + f16];
                }
            }
        }
        __syncthreads();

        // GEMM: 4 rows x 4 cols per thread, K=18
        int tx = tid & 15, ty = tid >> 4;
        int f0 = tx * 4, r0 = ty * 4;
        float4 acc[4];
        {
            float4 bv = make_float4(sb9[f0], sb9[f0 + 1], sb9[f0 + 2], sb9[f0 + 3]);
            #pragma unroll
            for (int i = 0; i < 4; i++) acc[i] = bv;
        }
        #pragma unroll
        for (int k = 0; k < 18; k++) {
            float4 w = *(const float4*)&sW9[k * 64 + f0];
            int ko = (k < 9) ? k : (k + 7);
            #pragma unroll
            for (int i = 0; i < 4; i++) {
                float a = sax9[(r0 + i) * 33 + ko];
                acc[i].x = fmaf(a, w.x, acc[i].x);
                acc[i].y = fmaf(a, w.y, acc[i].y);
                acc[i].z = fmaf(a, w.z, acc[i].z);
                acc[i].w = fmaf(a, w.w, acc[i].w);
            }
        }
        #pragma unroll
        for (int i = 0; i < 4; i++) {
            int row = row0 + r0 + i;
            if (row < ROWS) {
                float4 v = acc[i];
                v.x = elu_f(v.x); v.y = elu_f(v.y); v.z = elu_f(v.z); v.w = elu_f(v.w);
                *(float4*)(g_y1 + (long)row * 64 + f0) = v;
            }
        }
    }
}

// ---------------- host ------------------------------------------------------
extern "C" void kernel_launch(void* const* d_in, const int* in_sizes, int n_in,
                              void* d_out, int out_size) {
    const float* graph = (const float*)d_in[0];
    const float* tev   = (const float*)d_in[1];
    const float* ew    = (const float*)d_in[3];
    const int*   esrc  = (const int*)d_in[4];
    const int*   edst  = (const int*)d_in[5];
    const float* W1l = (const float*)d_in[6];
    const float* b1  = (const float*)d_in[7];
    const float* W1r = (const float*)d_in[8];
    const float* W2l = (const float*)d_in[9];
    const float* b2  = (const float*)d_in[10];
    const float* W2r = (const float*)d_in[11];
    const float* W3l = (const float*)d_in[12];
    const float* b3  = (const float*)d_in[13];
    const float* W3r = (const float*)d_in[14];
    const float* Wih = (const float*)d_in[15];
    const float* Whh = (const float*)d_in[16];
    const float* bih = (const float*)d_in[17];
    const float* bhh = (const float*)d_in[18];
    const float* encW = (const float*)d_in[19];
    const float* encb = (const float*)d_in[20];
    const float* decW = (const float*)d_in[21];
    const float* decb = (const float*)d_in[22];
    float* out = (float*)d_out;

    cudaFuncSetAttribute(lin64_kernel,
                         cudaFuncAttributeMaxDynamicSharedMemorySize, SM64_BYTES);

    prep_kernel<<<(XROWS + 255) / 256, 256>>>(graph, edst);
    scan_kernel<<<1, 1024>>>(encW, encb, decW, decb, tev);
    fill_kernel<<<(EE + 255) / 256, 256>>>(esrc, edst, ew);

    for (int t = 0; t < TT; t++) {
        int gb = (t == 0) ? 0 : GRU_BLOCKS;
        combo_kernel<<<gb + L9_BLOCKS, 256>>>(
            t - 1, gb, W1l, W1r, b1, b3, Wih, Whh, bih, bhh, out);
        lin64_kernel<<<K1_BLOCKS, 256, SM64_BYTES>>>(
            W2l + t * 4096, W2r + t * 4096, b2 + t * 64,
            W3l + t * 576, W3r + t * 576);
    }
    combo_kernel<<<GRU_BLOCKS, 256>>>(
        11, GRU_BLOCKS, W1l, W1r, b1, b3, Wih, Whh, bih, bhh, out);
}